// round 2
// baseline (speedup 1.0000x reference)
#include <cuda_runtime.h>
#include <math.h>

// ---------------------------------------------------------------------------
// AutoF1LSTM: 2-layer LSTM cell (H=2048, batch=1) + LN + 13 MLP heads.
// Memory-bound batch-1 matvecs. Layout constants:
#define H        2048
#define FOURH    8192
#define LIN      92          // 60 cont + 4*8 emb
#define NH       13
#define MAXO     9
// d_out layout: new_h[2*2048] | new_c[2*2048] | heads (27 floats)
#define OUT_C0   4096
#define OUT_H1   2048
#define OUT_C1   6144
#define OUT_HEAD 8192

// scratch (allocation-free rule: __device__ globals)
__device__ float g_gates0[FOURH];
__device__ float g_gates1[FOURH];
__device__ float g_hln[H];

__constant__ int c_head_outs[NH] = {5,1,1,1,1,1,1,1,9,1,3,1,1};
__constant__ int c_head_off[NH]  = {0,5,6,7,8,9,10,11,12,21,22,25,26};

__device__ __forceinline__ float sigf(float x) { return 1.0f / (1.0f + expf(-x)); }

__device__ __forceinline__ float warp_red(float v) {
    #pragma unroll
    for (int off = 16; off; off >>= 1) v += __shfl_down_sync(0xffffffffu, v, off);
    return v;
}

// ---------------------------------------------------------------------------
// K1: gates0 = W_ih0@x + b_ih0 + W_hh0@h_prev0 + b_hh0        (blocks 0..255)
//     gates1 = W_hh1@h_prev1 + b_hh1 + b_ih1  (partial)       (blocks 256..511)
// 256 threads (8 warps) per block, 4 rows per warp -> 32 rows/block.
__global__ void __launch_bounds__(256)
k_gates(const float* __restrict__ lap, const int* __restrict__ idx,
        const float* __restrict__ h_s,
        const float* __restrict__ emb_team, const float* __restrict__ emb_track,
        const float* __restrict__ emb_driver, const float* __restrict__ emb_comp,
        const float* __restrict__ Wih0, const float* __restrict__ Whh0,
        const float* __restrict__ bih0, const float* __restrict__ bhh0,
        const float* __restrict__ Whh1, const float* __restrict__ bih1,
        const float* __restrict__ bhh1)
{
    __shared__ float4 sh_h[H / 4];
    __shared__ __align__(16) float sh_x[LIN];

    const bool part1 = (blockIdx.x >= 256);
    const float* hvec = part1 ? (h_s + H) : h_s;
    const int tid = threadIdx.x;

    #pragma unroll
    for (int i = tid; i < H / 4; i += 256)
        sh_h[i] = reinterpret_cast<const float4*>(hvec)[i];

    if (!part1 && tid < LIN) {
        float v;
        if      (tid < 60) v = lap[tid];
        else if (tid < 68) v = emb_team  [idx[3] * 8 + (tid - 60)];
        else if (tid < 76) v = emb_track [idx[2] * 8 + (tid - 68)];
        else if (tid < 84) v = emb_driver[idx[1] * 8 + (tid - 76)];
        else               v = emb_comp  [idx[0] * 8 + (tid - 84)];
        sh_x[tid] = v;
    }
    __syncthreads();

    const int warp = tid >> 5, lane = tid & 31;
    const int rowbase = (blockIdx.x & 255) * 32 + warp * 4;
    const float* Whh = part1 ? Whh1 : Whh0;

    #pragma unroll
    for (int rr = 0; rr < 4; ++rr) {
        const int r = rowbase + rr;
        const float4* W4 = reinterpret_cast<const float4*>(Whh + (size_t)r * H);
        float acc = 0.f;
        #pragma unroll
        for (int it = 0; it < H / 128; ++it) {   // 16 iters
            float4 w = W4[it * 32 + lane];
            float4 hv = sh_h[it * 32 + lane];
            acc += w.x * hv.x + w.y * hv.y + w.z * hv.z + w.w * hv.w;
        }
        if (!part1 && lane < LIN / 4) {          // 23 float4
            float4 w = reinterpret_cast<const float4*>(Wih0 + (size_t)r * LIN)[lane];
            float4 xv = reinterpret_cast<const float4*>(sh_x)[lane];
            acc += w.x * xv.x + w.y * xv.y + w.z * xv.z + w.w * xv.w;
        }
        acc = warp_red(acc);
        if (lane == 0) {
            if (!part1) g_gates0[r] = acc + bih0[r] + bhh0[r];
            else        g_gates1[r] = acc + bih1[r] + bhh1[r];
        }
    }
}

// ---------------------------------------------------------------------------
// K2: layer-0 activations -> h0 (d_out[0:2048]), c0 (d_out[4096:6144])
__global__ void __launch_bounds__(1024)
k_act0(const float* __restrict__ c_s, float* __restrict__ out)
{
    const int j = blockIdx.x * 1024 + threadIdx.x;  // grid 2 x 1024
    float i  = sigf (g_gates0[j]);
    float f  = sigf (g_gates0[H + j]);
    float gg = tanhf(g_gates0[2 * H + j]);
    float o  = sigf (g_gates0[3 * H + j]);
    float c  = f * c_s[j] + i * gg;
    float h  = o * tanhf(c);
    out[OUT_C0 + j] = c;
    out[j] = h;
}

// ---------------------------------------------------------------------------
// K3: gates1 += W_ih1 @ h0     (h0 read from d_out[0:2048])
__global__ void __launch_bounds__(256)
k_gates1(const float* __restrict__ Wih1, const float* __restrict__ out)
{
    __shared__ float4 sh_h[H / 4];
    const int tid = threadIdx.x;
    #pragma unroll
    for (int i = tid; i < H / 4; i += 256)
        sh_h[i] = reinterpret_cast<const float4*>(out)[i];
    __syncthreads();

    const int warp = tid >> 5, lane = tid & 31;
    const int rowbase = blockIdx.x * 32 + warp * 4;
    #pragma unroll
    for (int rr = 0; rr < 4; ++rr) {
        const int r = rowbase + rr;
        const float4* W4 = reinterpret_cast<const float4*>(Wih1 + (size_t)r * H);
        float acc = 0.f;
        #pragma unroll
        for (int it = 0; it < H / 128; ++it) {
            float4 w = W4[it * 32 + lane];
            float4 hv = sh_h[it * 32 + lane];
            acc += w.x * hv.x + w.y * hv.y + w.z * hv.z + w.w * hv.w;
        }
        acc = warp_red(acc);
        if (lane == 0) g_gates1[r] += acc;
    }
}

// ---------------------------------------------------------------------------
// K4: layer-1 activations + LayerNorm. Single block, 1024 threads, 2 elems ea.
__global__ void __launch_bounds__(1024)
k_act1(const float* __restrict__ c_s, const float* __restrict__ ln_g,
       const float* __restrict__ ln_b, float* __restrict__ out)
{
    __shared__ float sh_h[H];
    __shared__ float red_s[32], red_q[32];
    const int tid = threadIdx.x;
    const float* c_prev = c_s + H;

    float hv[2];
    #pragma unroll
    for (int t = 0; t < 2; ++t) {
        const int j = tid + t * 1024;
        float i  = sigf (g_gates1[j]);
        float f  = sigf (g_gates1[H + j]);
        float gg = tanhf(g_gates1[2 * H + j]);
        float o  = sigf (g_gates1[3 * H + j]);
        float c  = f * c_prev[j] + i * gg;
        float h  = o * tanhf(c);
        out[OUT_C1 + j] = c;
        out[OUT_H1 + j] = h;
        sh_h[j] = h;
        hv[t] = h;
    }

    float s = hv[0] + hv[1];
    float q = hv[0] * hv[0] + hv[1] * hv[1];
    s = warp_red(s); q = warp_red(q);
    const int warp = tid >> 5, lane = tid & 31;
    if (lane == 0) { red_s[warp] = s; red_q[warp] = q; }
    __syncthreads();
    if (warp == 0) {
        s = red_s[lane]; q = red_q[lane];
        s = warp_red(s); q = warp_red(q);
        if (lane == 0) { red_s[0] = s; red_q[0] = q; }
    }
    __syncthreads();
    const float mu = red_s[0] * (1.0f / H);
    const float var = red_q[0] * (1.0f / H) - mu * mu;
    const float rstd = rsqrtf(var + 1e-5f);

    #pragma unroll
    for (int t = 0; t < 2; ++t) {
        const int j = tid + t * 1024;
        g_hln[j] = (sh_h[j] - mu) * rstd * ln_g[j] + ln_b[j];
    }
}

// ---------------------------------------------------------------------------
// K5: heads. One block per head (13 blocks, 512 threads = 16 warps).
__global__ void __launch_bounds__(512)
k_heads(const float* __restrict__ W1, const float* __restrict__ b1,
        const float* __restrict__ W2, const float* __restrict__ b2,
        float* __restrict__ out)
{
    __shared__ float4 sh_h[H / 4];
    __shared__ float sh_hid[64];
    const int k = blockIdx.x;
    const int tid = threadIdx.x;

    sh_h[tid] = reinterpret_cast<const float4*>(g_hln)[tid];  // 512 float4
    __syncthreads();

    const int warp = tid >> 5, lane = tid & 31;
    #pragma unroll
    for (int rr = 0; rr < 4; ++rr) {
        const int o = warp * 4 + rr;  // 0..63
        const float4* W4 = reinterpret_cast<const float4*>(
            W1 + ((size_t)k * 64 + o) * H);
        float acc = 0.f;
        #pragma unroll
        for (int it = 0; it < H / 128; ++it) {
            float4 w = W4[it * 32 + lane];
            float4 hv = sh_h[it * 32 + lane];
            acc += w.x * hv.x + w.y * hv.y + w.z * hv.z + w.w * hv.w;
        }
        acc = warp_red(acc);
        if (lane == 0) sh_hid[o] = fmaxf(acc + b1[k * 64 + o], 0.0f);
    }
    __syncthreads();

    const int nout = c_head_outs[k];
    if (warp < nout) {
        const float* w2 = W2 + ((size_t)k * MAXO + warp) * 64;
        float acc = sh_hid[lane] * w2[lane] + sh_hid[lane + 32] * w2[lane + 32];
        acc = warp_red(acc);
        if (lane == 0)
            out[OUT_HEAD + c_head_off[k] + warp] = acc + b2[k * MAXO + warp];
    }
}

// ---------------------------------------------------------------------------
extern "C" void kernel_launch(void* const* d_in, const int* in_sizes, int n_in,
                              void* d_out, int out_size)
{
    const float* lap        = (const float*)d_in[0];
    const int*   idx        = (const int*)  d_in[1];
    const float* h_s        = (const float*)d_in[2];
    const float* c_s        = (const float*)d_in[3];
    const float* emb_team   = (const float*)d_in[4];
    const float* emb_track  = (const float*)d_in[5];
    const float* emb_driver = (const float*)d_in[6];
    const float* emb_comp   = (const float*)d_in[7];
    const float* Wih0       = (const float*)d_in[8];
    const float* Whh0       = (const float*)d_in[9];
    const float* bih0       = (const float*)d_in[10];
    const float* bhh0       = (const float*)d_in[11];
    const float* Wih1       = (const float*)d_in[12];
    const float* Whh1       = (const float*)d_in[13];
    const float* bih1       = (const float*)d_in[14];
    const float* bhh1       = (const float*)d_in[15];
    const float* ln_g       = (const float*)d_in[16];
    const float* ln_b       = (const float*)d_in[17];
    const float* hW1        = (const float*)d_in[18];
    const float* hb1        = (const float*)d_in[19];
    const float* hW2        = (const float*)d_in[20];
    const float* hb2        = (const float*)d_in[21];
    float* out = (float*)d_out;

    k_gates<<<512, 256>>>(lap, idx, h_s, emb_team, emb_track, emb_driver,
                          emb_comp, Wih0, Whh0, bih0, bhh0, Whh1, bih1, bhh1);
    k_act0<<<2, 1024>>>(c_s, out);
    k_gates1<<<256, 256>>>(Wih1, out);
    k_act1<<<1, 1024>>>(c_s, ln_g, ln_b, out);
    k_heads<<<NH, 512>>>(hW1, hb1, hW2, hb2, out);
}

// round 3
// speedup vs baseline: 1.3168x; 1.3168x over previous
#include <cuda_runtime.h>
#include <math.h>

#define H        2048
#define FOURH    8192
#define LIN      92
#define NH       13
#define MAXO     9
#define OUT_C0   4096
#define OUT_H1   2048
#define OUT_C1   6144
#define OUT_HEAD 8192

__device__ float g_gates0[FOURH];
__device__ float g_gates1[FOURH];

__constant__ int c_head_outs[NH] = {5,1,1,1,1,1,1,1,9,1,3,1,1};
__constant__ int c_head_off[NH]  = {0,5,6,7,8,9,10,11,12,21,22,25,26};

__device__ __forceinline__ float sigf(float x) {
    return __fdividef(1.0f, 1.0f + __expf(-x));
}
__device__ __forceinline__ float tanh_fast(float x) {
    // safe at both extremes: expf->inf => 2/inf = 0 => 1 ; expf->0 => 1-2 = -1
    return 1.0f - __fdividef(2.0f, __expf(2.0f * x) + 1.0f);
}

__device__ __forceinline__ float warp_red(float v) {
    #pragma unroll
    for (int off = 16; off; off >>= 1) v += __shfl_down_sync(0xffffffffu, v, off);
    return v;
}

// ---------------------------------------------------------------------------
// K1: gates0 = W_ih0@x + b_ih0 + W_hh0@h_prev0 + b_hh0   (blocks 0..255)
//     gates1 = W_hh1@h_prev1 + b_ih1 + b_hh1  (partial)  (blocks 256..511)
__global__ void __launch_bounds__(256)
k_gates(const float* __restrict__ lap, const int* __restrict__ idx,
        const float* __restrict__ h_s,
        const float* __restrict__ emb_team, const float* __restrict__ emb_track,
        const float* __restrict__ emb_driver, const float* __restrict__ emb_comp,
        const float* __restrict__ Wih0, const float* __restrict__ Whh0,
        const float* __restrict__ bih0, const float* __restrict__ bhh0,
        const float* __restrict__ Whh1, const float* __restrict__ bih1,
        const float* __restrict__ bhh1)
{
    __shared__ float4 sh_h[H / 4];
    __shared__ __align__(16) float sh_x[LIN];

    const bool part1 = (blockIdx.x >= 256);
    const float* hvec = part1 ? (h_s + H) : h_s;
    const int tid = threadIdx.x;

    #pragma unroll
    for (int i = tid; i < H / 4; i += 256)
        sh_h[i] = reinterpret_cast<const float4*>(hvec)[i];

    if (!part1 && tid < LIN) {
        float v;
        if      (tid < 60) v = lap[tid];
        else if (tid < 68) v = emb_team  [idx[3] * 8 + (tid - 60)];
        else if (tid < 76) v = emb_track [idx[2] * 8 + (tid - 68)];
        else if (tid < 84) v = emb_driver[idx[1] * 8 + (tid - 76)];
        else               v = emb_comp  [idx[0] * 8 + (tid - 84)];
        sh_x[tid] = v;
    }
    __syncthreads();

    const int warp = tid >> 5, lane = tid & 31;
    const int rowbase = (blockIdx.x & 255) * 32 + warp * 4;
    const float* Whh = part1 ? Whh1 : Whh0;

    #pragma unroll
    for (int rp = 0; rp < 2; ++rp) {
        const int r0 = rowbase + rp * 2;
        const int r1 = r0 + 1;
        const float4* Wr0 = reinterpret_cast<const float4*>(Whh + (size_t)r0 * H);
        const float4* Wr1 = reinterpret_cast<const float4*>(Whh + (size_t)r1 * H);
        float a0 = 0.f, a1 = 0.f;
        #pragma unroll
        for (int it = 0; it < H / 128; ++it) {   // 16 iters, 2 rows in flight
            float4 w0 = __ldcs(Wr0 + it * 32 + lane);
            float4 w1 = __ldcs(Wr1 + it * 32 + lane);
            float4 hv = sh_h[it * 32 + lane];
            a0 += w0.x * hv.x + w0.y * hv.y + w0.z * hv.z + w0.w * hv.w;
            a1 += w1.x * hv.x + w1.y * hv.y + w1.z * hv.z + w1.w * hv.w;
        }
        if (!part1 && lane < LIN / 4) {          // 23 float4
            float4 xv = reinterpret_cast<const float4*>(sh_x)[lane];
            float4 w0 = __ldcs(reinterpret_cast<const float4*>(Wih0 + (size_t)r0 * LIN) + lane);
            float4 w1 = __ldcs(reinterpret_cast<const float4*>(Wih0 + (size_t)r1 * LIN) + lane);
            a0 += w0.x * xv.x + w0.y * xv.y + w0.z * xv.z + w0.w * xv.w;
            a1 += w1.x * xv.x + w1.y * xv.y + w1.z * xv.z + w1.w * xv.w;
        }
        a0 = warp_red(a0);
        a1 = warp_red(a1);
        if (lane == 0) {
            if (!part1) {
                g_gates0[r0] = a0 + bih0[r0] + bhh0[r0];
                g_gates0[r1] = a1 + bih0[r1] + bhh0[r1];
            } else {
                g_gates1[r0] = a0 + bih1[r0] + bhh1[r0];
                g_gates1[r1] = a1 + bih1[r1] + bhh1[r1];
            }
        }
    }
}

// ---------------------------------------------------------------------------
// K2: each block recomputes h0/c0 from gates0 (L2-resident, cheap), block 0
//     writes them to out; then gates1 += W_ih1 @ h0.
__global__ void __launch_bounds__(256)
k_l1(const float* __restrict__ Wih1, const float* __restrict__ c_s,
     float* __restrict__ out)
{
    __shared__ __align__(16) float sh_h[H];
    const int tid = threadIdx.x;

    #pragma unroll
    for (int j = tid; j < H; j += 256) {
        float i  = sigf(g_gates0[j]);
        float f  = sigf(g_gates0[H + j]);
        float gg = tanh_fast(g_gates0[2 * H + j]);
        float o  = sigf(g_gates0[3 * H + j]);
        float c  = f * c_s[j] + i * gg;
        float h  = o * tanh_fast(c);
        sh_h[j] = h;
        if (blockIdx.x == 0) { out[OUT_C0 + j] = c; out[j] = h; }
    }
    __syncthreads();

    const int warp = tid >> 5, lane = tid & 31;
    const int rowbase = blockIdx.x * 32 + warp * 4;
    const float4* shv = reinterpret_cast<const float4*>(sh_h);

    #pragma unroll
    for (int rp = 0; rp < 2; ++rp) {
        const int r0 = rowbase + rp * 2;
        const int r1 = r0 + 1;
        const float4* Wr0 = reinterpret_cast<const float4*>(Wih1 + (size_t)r0 * H);
        const float4* Wr1 = reinterpret_cast<const float4*>(Wih1 + (size_t)r1 * H);
        float a0 = 0.f, a1 = 0.f;
        #pragma unroll
        for (int it = 0; it < H / 128; ++it) {
            float4 w0 = __ldcs(Wr0 + it * 32 + lane);
            float4 w1 = __ldcs(Wr1 + it * 32 + lane);
            float4 hv = shv[it * 32 + lane];
            a0 += w0.x * hv.x + w0.y * hv.y + w0.z * hv.z + w0.w * hv.w;
            a1 += w1.x * hv.x + w1.y * hv.y + w1.z * hv.z + w1.w * hv.w;
        }
        a0 = warp_red(a0);
        a1 = warp_red(a1);
        if (lane == 0) {
            g_gates1[r0] += a0;
            g_gates1[r1] += a1;
        }
    }
}

// ---------------------------------------------------------------------------
// K3: one block per head (13 blocks, 1024 threads). Each block recomputes
//     h1/c1 + LayerNorm (block 0 also writes h1/c1 to out), then its head MLP.
__global__ void __launch_bounds__(1024)
k_heads(const float* __restrict__ c_s, const float* __restrict__ ln_g,
        const float* __restrict__ ln_b,
        const float* __restrict__ W1, const float* __restrict__ b1,
        const float* __restrict__ W2, const float* __restrict__ b2,
        float* __restrict__ out)
{
    __shared__ __align__(16) float sh_h[H];
    __shared__ float red_s[32], red_q[32];
    __shared__ float sh_hid[64];
    const int k = blockIdx.x;
    const int tid = threadIdx.x;
    const int warp = tid >> 5, lane = tid & 31;
    const float* c_prev = c_s + H;

    float s = 0.f, q = 0.f;
    #pragma unroll
    for (int t = 0; t < 2; ++t) {
        const int j = tid + t * 1024;
        float i  = sigf(g_gates1[j]);
        float f  = sigf(g_gates1[H + j]);
        float gg = tanh_fast(g_gates1[2 * H + j]);
        float o  = sigf(g_gates1[3 * H + j]);
        float c  = f * c_prev[j] + i * gg;
        float h  = o * tanh_fast(c);
        if (k == 0) { out[OUT_C1 + j] = c; out[OUT_H1 + j] = h; }
        sh_h[j] = h;
        s += h;
        q += h * h;
    }
    s = warp_red(s); q = warp_red(q);
    if (lane == 0) { red_s[warp] = s; red_q[warp] = q; }
    __syncthreads();
    if (warp == 0) {
        s = red_s[lane]; q = red_q[lane];
        s = warp_red(s); q = warp_red(q);
        if (lane == 0) { red_s[0] = s; red_q[0] = q; }
    }
    __syncthreads();
    const float mu   = red_s[0] * (1.0f / H);
    const float var  = red_q[0] * (1.0f / H) - mu * mu;
    const float rstd = rsqrtf(var + 1e-5f);

    #pragma unroll
    for (int t = 0; t < 2; ++t) {
        const int j = tid + t * 1024;
        sh_h[j] = (sh_h[j] - mu) * rstd * ln_g[j] + ln_b[j];
    }
    __syncthreads();

    // W1 matvec: 32 warps x 2 rows = 64 hidden units
    const float4* shv = reinterpret_cast<const float4*>(sh_h);
    #pragma unroll
    for (int rr = 0; rr < 2; ++rr) {
        const int o = warp * 2 + rr;  // 0..63
        const float4* W4 = reinterpret_cast<const float4*>(
            W1 + ((size_t)k * 64 + o) * H);
        float acc = 0.f;
        #pragma unroll
        for (int it = 0; it < H / 128; ++it) {
            float4 w  = __ldcs(W4 + it * 32 + lane);
            float4 hv = shv[it * 32 + lane];
            acc += w.x * hv.x + w.y * hv.y + w.z * hv.z + w.w * hv.w;
        }
        acc = warp_red(acc);
        if (lane == 0) sh_hid[o] = fmaxf(acc + b1[k * 64 + o], 0.0f);
    }
    __syncthreads();

    const int nout = c_head_outs[k];
    if (warp < nout) {
        const float* w2 = W2 + ((size_t)k * MAXO + warp) * 64;
        float acc = sh_hid[lane] * w2[lane] + sh_hid[lane + 32] * w2[lane + 32];
        acc = warp_red(acc);
        if (lane == 0)
            out[OUT_HEAD + c_head_off[k] + warp] = acc + b2[k * MAXO + warp];
    }
}

// ---------------------------------------------------------------------------
extern "C" void kernel_launch(void* const* d_in, const int* in_sizes, int n_in,
                              void* d_out, int out_size)
{
    const float* lap        = (const float*)d_in[0];
    const int*   idx        = (const int*)  d_in[1];
    const float* h_s        = (const float*)d_in[2];
    const float* c_s        = (const float*)d_in[3];
    const float* emb_team   = (const float*)d_in[4];
    const float* emb_track  = (const float*)d_in[5];
    const float* emb_driver = (const float*)d_in[6];
    const float* emb_comp   = (const float*)d_in[7];
    const float* Wih0       = (const float*)d_in[8];
    const float* Whh0       = (const float*)d_in[9];
    const float* bih0       = (const float*)d_in[10];
    const float* bhh0       = (const float*)d_in[11];
    const float* Wih1       = (const float*)d_in[12];
    const float* Whh1       = (const float*)d_in[13];
    const float* bih1       = (const float*)d_in[14];
    const float* bhh1       = (const float*)d_in[15];
    const float* ln_g       = (const float*)d_in[16];
    const float* ln_b       = (const float*)d_in[17];
    const float* hW1        = (const float*)d_in[18];
    const float* hb1        = (const float*)d_in[19];
    const float* hW2        = (const float*)d_in[20];
    const float* hb2        = (const float*)d_in[21];
    float* out = (float*)d_out;

    k_gates<<<512, 256>>>(lap, idx, h_s, emb_team, emb_track, emb_driver,
                          emb_comp, Wih0, Whh0, bih0, bhh0, Whh1, bih1, bhh1);
    k_l1<<<256, 256>>>(Wih1, c_s, out);
    k_heads<<<NH, 1024>>>(c_s, ln_g, ln_b, hW1, hb1, hW2, hb2, out);
}

// round 4
// speedup vs baseline: 1.3973x; 1.0611x over previous
#include <cuda_runtime.h>
#include <math.h>

#define H        2048
#define FOURH    8192
#define LIN      92
#define NH       13
#define MAXO     9
#define OUT_C0   4096
#define OUT_H1   2048
#define OUT_C1   6144
#define OUT_HEAD 8192
#define NOUT     27

__device__ float g_gates0[FOURH];
__device__ float g_gates1[FOURH];
__device__ float g_hid[NH * 64];

__constant__ int c_pair_k[NOUT] = {0,0,0,0,0, 1,2,3,4,5,6,7,
                                   8,8,8,8,8,8,8,8,8, 9, 10,10,10, 11, 12};
__constant__ int c_pair_p[NOUT] = {0,1,2,3,4, 0,0,0,0,0,0,0,
                                   0,1,2,3,4,5,6,7,8, 0, 0,1,2, 0, 0};

__device__ __forceinline__ float sigf(float x) {
    return __fdividef(1.0f, 1.0f + __expf(-x));
}
__device__ __forceinline__ float tanh_fast(float x) {
    return 1.0f - __fdividef(2.0f, __expf(2.0f * x) + 1.0f);
}
__device__ __forceinline__ float warp_red(float v) {
    #pragma unroll
    for (int off = 16; off; off >>= 1) v += __shfl_down_sync(0xffffffffu, v, off);
    return v;
}
__device__ __forceinline__ float dot4(float4 a, float4 b) {
    return a.x * b.x + a.y * b.y + a.z * b.z + a.w * b.w;
}

// ---------------------------------------------------------------------------
// K1: gates0 = W_ih0@x + b + W_hh0@h0_prev   (blocks 0..255)
//     gates1 = W_hh1@h1_prev + biases        (blocks 256..511)
// 8 warps/block, 4 rows per warp (4 independent LDG streams -> high MLP).
__global__ void __launch_bounds__(256)
k_gates(const float* __restrict__ lap, const int* __restrict__ idx,
        const float* __restrict__ h_s,
        const float* __restrict__ emb_team, const float* __restrict__ emb_track,
        const float* __restrict__ emb_driver, const float* __restrict__ emb_comp,
        const float* __restrict__ Wih0, const float* __restrict__ Whh0,
        const float* __restrict__ bih0, const float* __restrict__ bhh0,
        const float* __restrict__ Whh1, const float* __restrict__ bih1,
        const float* __restrict__ bhh1)
{
    __shared__ float4 sh_h[H / 4];
    __shared__ __align__(16) float sh_x[LIN];

    const bool part1 = (blockIdx.x >= 256);
    const float* hvec = part1 ? (h_s + H) : h_s;
    const int tid = threadIdx.x;

    #pragma unroll
    for (int i = tid; i < H / 4; i += 256)
        sh_h[i] = reinterpret_cast<const float4*>(hvec)[i];

    if (!part1 && tid < LIN) {
        float v;
        if      (tid < 60) v = lap[tid];
        else if (tid < 68) v = emb_team  [idx[3] * 8 + (tid - 60)];
        else if (tid < 76) v = emb_track [idx[2] * 8 + (tid - 68)];
        else if (tid < 84) v = emb_driver[idx[1] * 8 + (tid - 76)];
        else               v = emb_comp  [idx[0] * 8 + (tid - 84)];
        sh_x[tid] = v;
    }
    __syncthreads();

    const int warp = tid >> 5, lane = tid & 31;
    const int rowbase = (blockIdx.x & 255) * 32 + warp * 4;
    const float* Whh = part1 ? Whh1 : Whh0;

    const float4* Wr0 = reinterpret_cast<const float4*>(Whh + (size_t)(rowbase + 0) * H);
    const float4* Wr1 = reinterpret_cast<const float4*>(Whh + (size_t)(rowbase + 1) * H);
    const float4* Wr2 = reinterpret_cast<const float4*>(Whh + (size_t)(rowbase + 2) * H);
    const float4* Wr3 = reinterpret_cast<const float4*>(Whh + (size_t)(rowbase + 3) * H);

    float a0 = 0.f, a1 = 0.f, a2 = 0.f, a3 = 0.f;
    #pragma unroll
    for (int it = 0; it < H / 128; ++it) {   // 16 iters, 4 rows in flight
        const int o = it * 32 + lane;
        float4 w0 = __ldcs(Wr0 + o);
        float4 w1 = __ldcs(Wr1 + o);
        float4 w2 = __ldcs(Wr2 + o);
        float4 w3 = __ldcs(Wr3 + o);
        float4 hv = sh_h[o];
        a0 += dot4(w0, hv);
        a1 += dot4(w1, hv);
        a2 += dot4(w2, hv);
        a3 += dot4(w3, hv);
    }
    if (!part1 && lane < LIN / 4) {          // 23 float4
        float4 xv = reinterpret_cast<const float4*>(sh_x)[lane];
        a0 += dot4(__ldcs(reinterpret_cast<const float4*>(Wih0 + (size_t)(rowbase + 0) * LIN) + lane), xv);
        a1 += dot4(__ldcs(reinterpret_cast<const float4*>(Wih0 + (size_t)(rowbase + 1) * LIN) + lane), xv);
        a2 += dot4(__ldcs(reinterpret_cast<const float4*>(Wih0 + (size_t)(rowbase + 2) * LIN) + lane), xv);
        a3 += dot4(__ldcs(reinterpret_cast<const float4*>(Wih0 + (size_t)(rowbase + 3) * LIN) + lane), xv);
    }
    a0 = warp_red(a0); a1 = warp_red(a1); a2 = warp_red(a2); a3 = warp_red(a3);
    if (lane == 0) {
        if (!part1) {
            g_gates0[rowbase + 0] = a0 + bih0[rowbase + 0] + bhh0[rowbase + 0];
            g_gates0[rowbase + 1] = a1 + bih0[rowbase + 1] + bhh0[rowbase + 1];
            g_gates0[rowbase + 2] = a2 + bih0[rowbase + 2] + bhh0[rowbase + 2];
            g_gates0[rowbase + 3] = a3 + bih0[rowbase + 3] + bhh0[rowbase + 3];
        } else {
            g_gates1[rowbase + 0] = a0 + bih1[rowbase + 0] + bhh1[rowbase + 0];
            g_gates1[rowbase + 1] = a1 + bih1[rowbase + 1] + bhh1[rowbase + 1];
            g_gates1[rowbase + 2] = a2 + bih1[rowbase + 2] + bhh1[rowbase + 2];
            g_gates1[rowbase + 3] = a3 + bih1[rowbase + 3] + bhh1[rowbase + 3];
        }
    }
}

// ---------------------------------------------------------------------------
// K2: recompute h0/c0 from gates0 (L2-resident), block 0 writes them out;
//     then gates1 += W_ih1 @ h0.   256 blocks x 256 threads, 4 rows/warp.
__global__ void __launch_bounds__(256)
k_l1(const float* __restrict__ Wih1, const float* __restrict__ c_s,
     float* __restrict__ out)
{
    __shared__ __align__(16) float sh_h[H];
    const int tid = threadIdx.x;

    #pragma unroll
    for (int j = tid; j < H; j += 256) {
        float i  = sigf(g_gates0[j]);
        float f  = sigf(g_gates0[H + j]);
        float gg = tanh_fast(g_gates0[2 * H + j]);
        float o  = sigf(g_gates0[3 * H + j]);
        float c  = f * c_s[j] + i * gg;
        float h  = o * tanh_fast(c);
        sh_h[j] = h;
        if (blockIdx.x == 0) { out[OUT_C0 + j] = c; out[j] = h; }
    }
    __syncthreads();

    const int warp = tid >> 5, lane = tid & 31;
    const int rowbase = blockIdx.x * 32 + warp * 4;
    const float4* shv = reinterpret_cast<const float4*>(sh_h);

    const float4* Wr0 = reinterpret_cast<const float4*>(Wih1 + (size_t)(rowbase + 0) * H);
    const float4* Wr1 = reinterpret_cast<const float4*>(Wih1 + (size_t)(rowbase + 1) * H);
    const float4* Wr2 = reinterpret_cast<const float4*>(Wih1 + (size_t)(rowbase + 2) * H);
    const float4* Wr3 = reinterpret_cast<const float4*>(Wih1 + (size_t)(rowbase + 3) * H);

    float a0 = 0.f, a1 = 0.f, a2 = 0.f, a3 = 0.f;
    #pragma unroll
    for (int it = 0; it < H / 128; ++it) {
        const int o = it * 32 + lane;
        float4 w0 = __ldcs(Wr0 + o);
        float4 w1 = __ldcs(Wr1 + o);
        float4 w2 = __ldcs(Wr2 + o);
        float4 w3 = __ldcs(Wr3 + o);
        float4 hv = shv[o];
        a0 += dot4(w0, hv);
        a1 += dot4(w1, hv);
        a2 += dot4(w2, hv);
        a3 += dot4(w3, hv);
    }
    a0 = warp_red(a0); a1 = warp_red(a1); a2 = warp_red(a2); a3 = warp_red(a3);
    if (lane == 0) {
        g_gates1[rowbase + 0] += a0;
        g_gates1[rowbase + 1] += a1;
        g_gates1[rowbase + 2] += a2;
        g_gates1[rowbase + 3] += a3;
    }
}

// ---------------------------------------------------------------------------
// K3: 104 blocks = 13 heads x 8 slices, 256 threads. Each block recomputes
//     h1/c1 + LN (head 0 slice 0 writes h1/c1 out), then its 8 W1 rows.
__global__ void __launch_bounds__(256)
k_hid(const float* __restrict__ c_s, const float* __restrict__ ln_g,
      const float* __restrict__ ln_b,
      const float* __restrict__ W1, const float* __restrict__ b1,
      float* __restrict__ out)
{
    __shared__ __align__(16) float sh_h[H];
    __shared__ float red_s[8], red_q[8];
    const int k = blockIdx.x >> 3;
    const int slice = blockIdx.x & 7;
    const int tid = threadIdx.x;
    const int warp = tid >> 5, lane = tid & 31;
    const float* c_prev = c_s + H;

    float s = 0.f, q = 0.f;
    #pragma unroll
    for (int t = 0; t < 8; ++t) {
        const int j = tid + t * 256;
        float i  = sigf(g_gates1[j]);
        float f  = sigf(g_gates1[H + j]);
        float gg = tanh_fast(g_gates1[2 * H + j]);
        float o  = sigf(g_gates1[3 * H + j]);
        float c  = f * c_prev[j] + i * gg;
        float h  = o * tanh_fast(c);
        if (blockIdx.x == 0) { out[OUT_C1 + j] = c; out[OUT_H1 + j] = h; }
        sh_h[j] = h;
        s += h;
        q += h * h;
    }
    s = warp_red(s); q = warp_red(q);
    if (lane == 0) { red_s[warp] = s; red_q[warp] = q; }
    __syncthreads();
    if (tid == 0) {
        float ss = 0.f, qq = 0.f;
        #pragma unroll
        for (int w = 0; w < 8; ++w) { ss += red_s[w]; qq += red_q[w]; }
        red_s[0] = ss; red_q[0] = qq;
    }
    __syncthreads();
    const float mu   = red_s[0] * (1.0f / H);
    const float var  = red_q[0] * (1.0f / H) - mu * mu;
    const float rstd = rsqrtf(var + 1e-5f);

    #pragma unroll
    for (int t = 0; t < 8; ++t) {
        const int j = tid + t * 256;
        sh_h[j] = (sh_h[j] - mu) * rstd * ln_g[j] + ln_b[j];
    }
    __syncthreads();

    // 8 warps x 1 row = 8 hidden units for this slice
    const int o = slice * 8 + warp;            // 0..63 within head
    const float4* W4 = reinterpret_cast<const float4*>(
        W1 + ((size_t)k * 64 + o) * H);
    const float4* shv = reinterpret_cast<const float4*>(sh_h);
    float acc = 0.f;
    #pragma unroll
    for (int it = 0; it < H / 128; ++it) {
        float4 w  = __ldcs(W4 + it * 32 + lane);
        float4 hv = shv[it * 32 + lane];
        acc += dot4(w, hv);
    }
    acc = warp_red(acc);
    if (lane == 0)
        g_hid[k * 64 + o] = fmaxf(acc + b1[k * 64 + o], 0.0f);
}

// ---------------------------------------------------------------------------
// K4: final W2. One block, warp per output (27 outputs).
__global__ void __launch_bounds__(NOUT * 32)
k_out(const float* __restrict__ W2, const float* __restrict__ b2,
      float* __restrict__ out)
{
    const int warp = threadIdx.x >> 5, lane = threadIdx.x & 31;
    const int k = c_pair_k[warp], p = c_pair_p[warp];
    const float* hid = g_hid + k * 64;
    const float* w2  = W2 + ((size_t)k * MAXO + p) * 64;
    float acc = hid[lane] * w2[lane] + hid[lane + 32] * w2[lane + 32];
    acc = warp_red(acc);
    if (lane == 0)
        out[OUT_HEAD + warp] = acc + b2[k * MAXO + p];
}

// ---------------------------------------------------------------------------
extern "C" void kernel_launch(void* const* d_in, const int* in_sizes, int n_in,
                              void* d_out, int out_size)
{
    const float* lap        = (const float*)d_in[0];
    const int*   idx        = (const int*)  d_in[1];
    const float* h_s        = (const float*)d_in[2];
    const float* c_s        = (const float*)d_in[3];
    const float* emb_team   = (const float*)d_in[4];
    const float* emb_track  = (const float*)d_in[5];
    const float* emb_driver = (const float*)d_in[6];
    const float* emb_comp   = (const float*)d_in[7];
    const float* Wih0       = (const float*)d_in[8];
    const float* Whh0       = (const float*)d_in[9];
    const float* bih0       = (const float*)d_in[10];
    const float* bhh0       = (const float*)d_in[11];
    const float* Wih1       = (const float*)d_in[12];
    const float* Whh1       = (const float*)d_in[13];
    const float* bih1       = (const float*)d_in[14];
    const float* bhh1       = (const float*)d_in[15];
    const float* ln_g       = (const float*)d_in[16];
    const float* ln_b       = (const float*)d_in[17];
    const float* hW1        = (const float*)d_in[18];
    const float* hb1        = (const float*)d_in[19];
    const float* hW2        = (const float*)d_in[20];
    const float* hb2        = (const float*)d_in[21];
    float* out = (float*)d_out;

    k_gates<<<512, 256>>>(lap, idx, h_s, emb_team, emb_track, emb_driver,
                          emb_comp, Wih0, Whh0, bih0, bhh0, Whh1, bih1, bhh1);
    k_l1<<<256, 256>>>(Wih1, c_s, out);
    k_hid<<<NH * 8, 256>>>(c_s, ln_g, ln_b, hW1, hb1, out);
    k_out<<<1, NOUT * 32>>>(hW2, hb2, out);
}

// round 5
// speedup vs baseline: 1.5158x; 1.0848x over previous
#include <cuda_runtime.h>

#define H        2048
#define H4       (H/4)
#define FOURH    8192
#define LIN      92
#define NH       13
#define MAXO     9
#define NOUT     27
#define GRID     256
#define TPB      256
#define OUT_C0   4096
#define OUT_H1   2048
#define OUT_C1   6144
#define OUT_HEAD 8192

__device__ float g_gates0[FOURH];
__device__ float g_gates1[FOURH];
__device__ float g_hid[NH * 64];
__device__ unsigned g_cnt0 = 0, g_cnt1 = 0, g_cnt2 = 0;

__constant__ int c_pair_k[NOUT] = {0,0,0,0,0, 1,2,3,4,5,6,7,
                                   8,8,8,8,8,8,8,8,8, 9, 10,10,10, 11, 12};
__constant__ int c_pair_p[NOUT] = {0,1,2,3,4, 0,0,0,0,0,0,0,
                                   0,1,2,3,4,5,6,7,8, 0, 0,1,2, 0, 0};

__device__ __forceinline__ float sigf(float x) {
    return __fdividef(1.0f, 1.0f + __expf(-x));
}
__device__ __forceinline__ float tanh_fast(float x) {
    return 1.0f - __fdividef(2.0f, __expf(2.0f * x) + 1.0f);
}
__device__ __forceinline__ float warp_red(float v) {
    #pragma unroll
    for (int off = 16; off; off >>= 1) v += __shfl_down_sync(0xffffffffu, v, off);
    return v;
}
__device__ __forceinline__ float dot4(float4 a, float4 b) {
    return a.x * b.x + a.y * b.y + a.z * b.z + a.w * b.w;
}

// Grid-wide barrier. All GRID blocks are co-resident (launch_bounds(256,2)
// guarantees >=2 blocks/SM schedulable; 2*148=296 >= 256), so spinning is safe.
// The last arriver optionally resets the PREVIOUS barrier's counter (all
// blocks are provably past it).
__device__ __forceinline__ void grid_bar(unsigned* cnt, unsigned* reset_prev) {
    __syncthreads();
    if (threadIdx.x == 0) {
        __threadfence();
        unsigned tok = atomicAdd(cnt, 1u);
        if (tok == GRID - 1 && reset_prev)
            *(volatile unsigned*)reset_prev = 0u;
        while (*(volatile unsigned*)cnt < (unsigned)GRID) __nanosleep(32);
        __threadfence();
    }
    __syncthreads();
}

// ---------------------------------------------------------------------------
__global__ void __launch_bounds__(TPB, 2)
k_all(const float* __restrict__ lap, const int* __restrict__ idx,
      const float* __restrict__ h_s, const float* __restrict__ c_s,
      const float* __restrict__ emb_team, const float* __restrict__ emb_track,
      const float* __restrict__ emb_driver, const float* __restrict__ emb_comp,
      const float* __restrict__ Wih0, const float* __restrict__ Whh0,
      const float* __restrict__ bih0, const float* __restrict__ bhh0,
      const float* __restrict__ Wih1, const float* __restrict__ Whh1,
      const float* __restrict__ bih1, const float* __restrict__ bhh1,
      const float* __restrict__ ln_g, const float* __restrict__ ln_b,
      const float* __restrict__ W1,  const float* __restrict__ b1,
      const float* __restrict__ W2,  const float* __restrict__ b2,
      float* __restrict__ out)
{
    __shared__ __align__(16) float sh[H];
    __shared__ __align__(16) float sh_x[96];
    __shared__ float red_s[8], red_q[8];
    __shared__ unsigned s_tok;

    const int tid  = threadIdx.x;
    const int warp = tid >> 5, lane = tid & 31;
    const int b    = blockIdx.x;
    float4* sh4 = reinterpret_cast<float4*>(sh);

    // ======================= Phase A: big matvecs =========================
    {
        const bool part1 = (b >= 128);
        const float* hvec = part1 ? (h_s + H) : h_s;
        sh4[tid]       = reinterpret_cast<const float4*>(hvec)[tid];
        sh4[tid + 256] = reinterpret_cast<const float4*>(hvec)[tid + 256];
        if (!part1 && tid < LIN) {
            float v;
            if      (tid < 60) v = lap[tid];
            else if (tid < 68) v = emb_team  [idx[3] * 8 + (tid - 60)];
            else if (tid < 76) v = emb_track [idx[2] * 8 + (tid - 68)];
            else if (tid < 84) v = emb_driver[idx[1] * 8 + (tid - 76)];
            else               v = emb_comp  [idx[0] * 8 + (tid - 84)];
            sh_x[tid] = v;
        }
        __syncthreads();

        const int rowbase = (b & 127) * 64 + warp * 8;
        const float* W = part1 ? Whh1 : Whh0;
        const float4* Wr = reinterpret_cast<const float4*>(W) + (size_t)rowbase * H4;

        float acc[8] = {0.f,0.f,0.f,0.f,0.f,0.f,0.f,0.f};
        #pragma unroll
        for (int it = 0; it < 16; ++it) {
            const int o = it * 32 + lane;
            float4 hv = sh4[o];
            #pragma unroll
            for (int r = 0; r < 8; ++r) {
                float4 w = __ldcs(Wr + r * H4 + o);
                acc[r] += dot4(w, hv);
            }
        }
        if (!part1 && lane < LIN / 4) {   // 23 float4 of x
            float4 xv = reinterpret_cast<const float4*>(sh_x)[lane];
            #pragma unroll
            for (int r = 0; r < 8; ++r) {
                float4 w = __ldcs(reinterpret_cast<const float4*>(
                                      Wih0 + (size_t)(rowbase + r) * LIN) + lane);
                acc[r] += dot4(w, xv);
            }
        }
        #pragma unroll
        for (int r = 0; r < 8; ++r) acc[r] = warp_red(acc[r]);
        if (lane == 0) {
            #pragma unroll
            for (int r = 0; r < 8; ++r) {
                const int row = rowbase + r;
                if (!part1) g_gates0[row] = acc[r] + bih0[row] + bhh0[row];
                else        g_gates1[row] = acc[r] + bih1[row] + bhh1[row];
            }
        }
    }
    grid_bar(&g_cnt0, nullptr);

    // ======== Phase B: h0/c0 recompute + gates1 += Wih1 @ h0 ==============
    {
        #pragma unroll
        for (int t = 0; t < 8; ++t) {
            const int j = tid + t * 256;
            float i  = sigf(g_gates0[j]);
            float f  = sigf(g_gates0[H + j]);
            float gg = tanh_fast(g_gates0[2 * H + j]);
            float o  = sigf(g_gates0[3 * H + j]);
            float c  = f * c_s[j] + i * gg;
            float h  = o * tanh_fast(c);
            sh[j] = h;
            if (b == 0) { out[OUT_C0 + j] = c; out[j] = h; }
        }
        __syncthreads();

        const int rowbase = b * 32 + warp * 4;
        const float4* Wr = reinterpret_cast<const float4*>(Wih1) + (size_t)rowbase * H4;
        float acc[4] = {0.f,0.f,0.f,0.f};
        #pragma unroll
        for (int it = 0; it < 16; ++it) {
            const int o = it * 32 + lane;
            float4 hv = sh4[o];
            #pragma unroll
            for (int r = 0; r < 4; ++r) {
                float4 w = __ldcs(Wr + r * H4 + o);
                acc[r] += dot4(w, hv);
            }
        }
        #pragma unroll
        for (int r = 0; r < 4; ++r) acc[r] = warp_red(acc[r]);
        if (lane == 0) {
            #pragma unroll
            for (int r = 0; r < 4; ++r)
                g_gates1[rowbase + r] += acc[r];
        }
    }
    grid_bar(&g_cnt1, &g_cnt0);

    // ======== Phase C: h1/c1 + LN recompute + head W1 (blocks 0..103) =====
    if (b < 104) {
        const float* c_prev = c_s + H;
        float s = 0.f, q = 0.f;
        #pragma unroll
        for (int t = 0; t < 8; ++t) {
            const int j = tid + t * 256;
            float i  = sigf(g_gates1[j]);
            float f  = sigf(g_gates1[H + j]);
            float gg = tanh_fast(g_gates1[2 * H + j]);
            float o  = sigf(g_gates1[3 * H + j]);
            float c  = f * c_prev[j] + i * gg;
            float h  = o * tanh_fast(c);
            if (b == 0) { out[OUT_C1 + j] = c; out[OUT_H1 + j] = h; }
            sh[j] = h;
            s += h;
            q += h * h;
        }
        s = warp_red(s); q = warp_red(q);
        if (lane == 0) { red_s[warp] = s; red_q[warp] = q; }
        __syncthreads();
        if (tid == 0) {
            float ss = 0.f, qq = 0.f;
            #pragma unroll
            for (int w = 0; w < 8; ++w) { ss += red_s[w]; qq += red_q[w]; }
            red_s[0] = ss; red_q[0] = qq;
        }
        __syncthreads();
        const float mu   = red_s[0] * (1.0f / H);
        const float var  = red_q[0] * (1.0f / H) - mu * mu;
        const float rstd = rsqrtf(var + 1e-5f);
        #pragma unroll
        for (int t = 0; t < 8; ++t) {
            const int j = tid + t * 256;
            sh[j] = (sh[j] - mu) * rstd * ln_g[j] + ln_b[j];
        }
        __syncthreads();

        const int g = b * 8 + warp;        // 0..831 = NH*64 rows
        const float4* W4 = reinterpret_cast<const float4*>(W1 + (size_t)g * H);
        float acc = 0.f;
        #pragma unroll
        for (int it = 0; it < 16; ++it) {
            float4 w  = __ldcs(W4 + it * 32 + lane);
            float4 hv = sh4[it * 32 + lane];
            acc += dot4(w, hv);
        }
        acc = warp_red(acc);
        if (lane == 0)
            g_hid[g] = fmaxf(acc + b1[g], 0.0f);
    }

    // ============ completion count; last block computes W2 ================
    __syncthreads();
    if (tid == 0) { __threadfence(); s_tok = atomicAdd(&g_cnt2, 1u); }
    __syncthreads();

    if (s_tok == GRID - 1) {           // last block: all g_hid visible
        __threadfence();
        for (int j = warp; j < NOUT; j += 8) {
            const int k = c_pair_k[j], p = c_pair_p[j];
            const float* hid = g_hid + k * 64;
            const float* w2  = W2 + ((size_t)k * MAXO + p) * 64;
            float acc = hid[lane] * w2[lane] + hid[lane + 32] * w2[lane + 32];
            acc = warp_red(acc);
            if (lane == 0)
                out[OUT_HEAD + j] = acc + b2[k * MAXO + p];
        }
        __syncthreads();
        if (tid == 0) {                // clean state for next graph replay
            *(volatile unsigned*)&g_cnt1 = 0u;
            *(volatile unsigned*)&g_cnt2 = 0u;
            __threadfence();
        }
    }
}

// ---------------------------------------------------------------------------
extern "C" void kernel_launch(void* const* d_in, const int* in_sizes, int n_in,
                              void* d_out, int out_size)
{
    const float* lap        = (const float*)d_in[0];
    const int*   idx        = (const int*)  d_in[1];
    const float* h_s        = (const float*)d_in[2];
    const float* c_s        = (const float*)d_in[3];
    const float* emb_team   = (const float*)d_in[4];
    const float* emb_track  = (const float*)d_in[5];
    const float* emb_driver = (const float*)d_in[6];
    const float* emb_comp   = (const float*)d_in[7];
    const float* Wih0       = (const float*)d_in[8];
    const float* Whh0       = (const float*)d_in[9];
    const float* bih0       = (const float*)d_in[10];
    const float* bhh0       = (const float*)d_in[11];
    const float* Wih1       = (const float*)d_in[12];
    const float* Whh1       = (const float*)d_in[13];
    const float* bih1       = (const float*)d_in[14];
    const float* bhh1       = (const float*)d_in[15];
    const float* ln_g       = (const float*)d_in[16];
    const float* ln_b       = (const float*)d_in[17];
    const float* hW1        = (const float*)d_in[18];
    const float* hb1        = (const float*)d_in[19];
    const float* hW2        = (const float*)d_in[20];
    const float* hb2        = (const float*)d_in[21];
    float* out = (float*)d_out;

    k_all<<<GRID, TPB>>>(lap, idx, h_s, c_s, emb_team, emb_track, emb_driver,
                         emb_comp, Wih0, Whh0, bih0, bhh0, Wih1, Whh1, bih1,
                         bhh1, ln_g, ln_b, hW1, hb1, hW2, hb2, out);
}